// round 1
// baseline (speedup 1.0000x reference)
#include <cuda_runtime.h>

// ---------------- configuration ----------------
#define THREADS 128
#define TILE    512          // database points per CTA tile
#define RQ      8            // queries per thread

#define CAP_F 16384
#define CAP_C 2048

// flag array sections
#define F_REFF   0
#define F_SRCFT  16384
#define F_REFC   32768
#define F_SRCCT  34816
#define FLAGS_TOTAL 36864

typedef unsigned long long ull;

// ---------------- device scratch (no allocation allowed) ----------------
__device__ float4 g_reff [CAP_F];   // ref_points_f       (x,y,z, -0.5*|p|^2)
__device__ float4 g_srcft[CAP_F];   // transformed src_f  (x,y,z, -0.5*|p|^2)
__device__ float4 g_refc [CAP_C];   // ref_points_c
__device__ float4 g_srcct[CAP_C];   // transformed src_c
__device__ int    g_flags[FLAGS_TOTAL];
__device__ float  g_acc[8];         // [0..2]=p2p (S1,Sp,Sn), [3..5]=n2p

// ---------------- packed f32x2 helpers ----------------
__device__ __forceinline__ ull pack2(float a, float b) {
    ull r; asm("mov.b64 %0, {%1,%2};" : "=l"(r) : "f"(a), "f"(b)); return r;
}
__device__ __forceinline__ void unpack2(ull v, float& a, float& b) {
    asm("mov.b64 {%0,%1}, %2;" : "=f"(a), "=f"(b) : "l"(v));
}
__device__ __forceinline__ ull fma2(ull a, ull b, ull c) {
    ull d; asm("fma.rn.f32x2 %0, %1, %2, %3;" : "=l"(d) : "l"(a), "l"(b), "l"(c));
    return d;
}

// ---------------- zero scratch ----------------
__global__ void zero_kernel() {
    int i = blockIdx.x * blockDim.x + threadIdx.x;
    if (i < FLAGS_TOTAL) g_flags[i] = 0;
    if (i < 8) g_acc[i] = 0.0f;
}

// ---------------- prep: transform + precompute h = -0.5|p|^2 ----------------
__global__ void prep_kernel(const float* __restrict__ rf, int Nf,
                            const float* __restrict__ sf, int Mf,
                            const float* __restrict__ rc, int Nc,
                            const float* __restrict__ sc, int Mc,
                            const float* __restrict__ T) {
    int i = blockIdx.x * blockDim.x + threadIdx.x;
    if (i < Nf) {
        float x = rf[3*i], y = rf[3*i+1], z = rf[3*i+2];
        g_reff[i] = make_float4(x, y, z, -0.5f*(x*x + y*y + z*z));
    } else if (i < Nf + Mf) {
        int j = i - Nf;
        float px = sf[3*j], py = sf[3*j+1], pz = sf[3*j+2];
        float x = T[0]*px + T[1]*py + T[2]*pz  + T[3];
        float y = T[4]*px + T[5]*py + T[6]*pz  + T[7];
        float z = T[8]*px + T[9]*py + T[10]*pz + T[11];
        g_srcft[j] = make_float4(x, y, z, -0.5f*(x*x + y*y + z*z));
    } else if (i < Nf + Mf + Nc) {
        int j = i - Nf - Mf;
        float x = rc[3*j], y = rc[3*j+1], z = rc[3*j+2];
        g_refc[j] = make_float4(x, y, z, -0.5f*(x*x + y*y + z*z));
    } else if (i < Nf + Mf + Nc + Mc) {
        int j = i - Nf - Mf - Nc;
        float px = sc[3*j], py = sc[3*j+1], pz = sc[3*j+2];
        float x = T[0]*px + T[1]*py + T[2]*pz  + T[3];
        float y = T[4]*px + T[5]*py + T[6]*pz  + T[7];
        float z = T[8]*px + T[9]*py + T[10]*pz + T[11];
        g_srcct[j] = make_float4(x, y, z, -0.5f*(x*x + y*y + z*z));
    }
}

// ---------------- flag kernel ----------------
// For query i: flag[i] = 1 iff exists db point j with |q_i - y_j| < thr
//   <=>  max_j ( q_i . y_j + h_j ) > c_i,   c_i = -h_qi - 0.5*thr^2
// MODE 0: fine (job0: q=reff vs db=srcft ; job1: q=srcft vs db=reff)
// MODE 1: coarse (job0: q=refc vs db=srcft ; job1: q=srcct vs db=reff)
template<int MODE>
__global__ __launch_bounds__(THREADS)
void flag_kernel(int nq0, int nq1, int ndb0, int ndb1, float halfthr2) {
    __shared__ ull sx[TILE/2], sy[TILE/2], sz[TILE/2], sw[TILE/2];

    int job = blockIdx.y;
    const float4* q;  const float4* db;  int* flags;  int nq, ndb;
    if (MODE == 0) {
        q     = job ? g_srcft : g_reff;
        db    = job ? g_reff  : g_srcft;
        flags = g_flags + (job ? F_SRCFT : F_REFF);
    } else {
        q     = job ? g_srcct : g_refc;
        db    = job ? g_reff  : g_srcft;
        flags = g_flags + (job ? F_SRCCT : F_REFC);
    }
    nq  = job ? nq1  : nq0;
    ndb = job ? ndb1 : ndb0;

    int t = threadIdx.x;
    int dbase = blockIdx.z * TILE;

    // cooperative tile load: 128 threads x 4 points each, transposed+packed
    #pragma unroll
    for (int u = 0; u < 2; u++) {
        int slot = 2*t + u;                    // pair slot (covers 2 db points)
        int gi = dbase + 2*slot;
        float4 d0 = (gi     < ndb) ? db[gi]   : make_float4(0.f,0.f,0.f,-1e30f);
        float4 d1 = (gi + 1 < ndb) ? db[gi+1] : make_float4(0.f,0.f,0.f,-1e30f);
        sx[slot] = pack2(d0.x, d1.x);
        sy[slot] = pack2(d0.y, d1.y);
        sz[slot] = pack2(d0.z, d1.z);
        sw[slot] = pack2(d0.w, d1.w);
    }

    int qbase = blockIdx.x * (THREADS * RQ);
    ull  qx2[RQ], qy2[RQ], qz2[RQ];
    float c[RQ], mlo[RQ], mhi[RQ];
    #pragma unroll
    for (int r = 0; r < RQ; r++) {
        int qi = qbase + r*THREADS + t;
        float4 Q = q[(qi < nq) ? qi : 0];
        qx2[r] = pack2(Q.x, Q.x);
        qy2[r] = pack2(Q.y, Q.y);
        qz2[r] = pack2(Q.z, Q.z);
        c[r]   = -Q.w - halfthr2;
        mlo[r] = -3e38f;
        mhi[r] = -3e38f;
    }
    __syncthreads();

    #pragma unroll 2
    for (int k = 0; k < TILE/2; k++) {
        ull yx = sx[k], yy = sy[k], yz = sz[k], yw = sw[k];
        #pragma unroll
        for (int r = 0; r < RQ; r++) {
            ull tt = fma2(qz2[r], yz, yw);
            tt     = fma2(qy2[r], yy, tt);
            tt     = fma2(qx2[r], yx, tt);
            float lo, hi; unpack2(tt, lo, hi);
            mlo[r] = fmaxf(mlo[r], lo);
            mhi[r] = fmaxf(mhi[r], hi);
        }
    }

    #pragma unroll
    for (int r = 0; r < RQ; r++) {
        int qi = qbase + r*THREADS + t;
        if (qi < nq && fmaxf(mlo[r], mhi[r]) > c[r]) flags[qi] = 1;  // benign race: all write 1
    }
}

// ---------------- reduce: accumulate (sum_gt, sum_pos_bce, sum_neg_bce) x2 ----------------
__global__ void reduce_kernel(const float* __restrict__ p2p_ref,
                              const float* __restrict__ p2p_src,
                              const float* __restrict__ n2p_ref,
                              const float* __restrict__ n2p_src,
                              int Nf, int Mf, int Nc, int Mc) {
    int i = blockIdx.x * blockDim.x + threadIdx.x;
    float v0 = 0.f, v1 = 0.f, v2 = 0.f, v3 = 0.f, v4 = 0.f, v5 = 0.f;

    if (i < Mf + Nf) {   // concat order: [src scores | ref scores]
        float pred; int gt;
        if (i < Mf) { pred = p2p_src[i];      gt = g_flags[F_SRCFT + i]; }
        else        { pred = p2p_ref[i - Mf]; gt = g_flags[F_REFF + (i - Mf)]; }
        float bce = gt ? -logf(pred) : -log1pf(-pred);
        v0 = (float)gt;
        v1 = gt ? bce : 0.f;
        v2 = gt ? 0.f : bce;
    }
    if (i < Mc + Nc) {
        float pred; int gt;
        if (i < Mc) { pred = n2p_src[i];      gt = g_flags[F_SRCCT + i]; }
        else        { pred = n2p_ref[i - Mc]; gt = g_flags[F_REFC + (i - Mc)]; }
        float bce = gt ? -logf(pred) : -log1pf(-pred);
        v3 = (float)gt;
        v4 = gt ? bce : 0.f;
        v5 = gt ? 0.f : bce;
    }

    #pragma unroll
    for (int off = 16; off; off >>= 1) {
        v0 += __shfl_down_sync(0xffffffffu, v0, off);
        v1 += __shfl_down_sync(0xffffffffu, v1, off);
        v2 += __shfl_down_sync(0xffffffffu, v2, off);
        v3 += __shfl_down_sync(0xffffffffu, v3, off);
        v4 += __shfl_down_sync(0xffffffffu, v4, off);
        v5 += __shfl_down_sync(0xffffffffu, v5, off);
    }
    if ((threadIdx.x & 31) == 0) {
        atomicAdd(&g_acc[0], v0);
        atomicAdd(&g_acc[1], v1);
        atomicAdd(&g_acc[2], v2);
        atomicAdd(&g_acc[3], v3);
        atomicAdd(&g_acc[4], v4);
        atomicAdd(&g_acc[5], v5);
    }
}

// ---------------- finalize ----------------
__global__ void finalize_kernel(float* out, int np2p, int nn2p) {
    if (threadIdx.x == 0 && blockIdx.x == 0) {
        float S1 = g_acc[0], Sp = g_acc[1], Sn = g_acc[2];
        float wneg = S1 / (float)np2p;
        float wpos = 1.0f - wneg;
        float p2p = (wpos * Sp + wneg * Sn) / (float)np2p;

        S1 = g_acc[3]; Sp = g_acc[4]; Sn = g_acc[5];
        float wneg2 = S1 / (float)nn2p;
        float wpos2 = 1.0f - wneg2;
        float n2p = (wpos2 * Sp + wneg2 * Sn) / (float)nn2p;

        out[0] = n2p;
        out[1] = p2p;
    }
}

static inline int imax_(int a, int b) { return a > b ? a : b; }

extern "C" void kernel_launch(void* const* d_in, const int* in_sizes, int n_in,
                              void* d_out, int out_size) {
    const float* rc = (const float*)d_in[0]; int Nc = in_sizes[0] / 3;
    const float* sc = (const float*)d_in[1]; int Mc = in_sizes[1] / 3;
    const float* rf = (const float*)d_in[2]; int Nf = in_sizes[2] / 3;
    const float* sf = (const float*)d_in[3]; int Mf = in_sizes[3] / 3;
    const float* T  = (const float*)d_in[4];
    const float* p2p_ref = (const float*)d_in[5];
    const float* p2p_src = (const float*)d_in[6];
    const float* n2p_ref = (const float*)d_in[7];
    const float* n2p_src = (const float*)d_in[8];
    float* out = (float*)d_out;

    if (Nf > CAP_F) Nf = CAP_F;
    if (Mf > CAP_F) Mf = CAP_F;
    if (Nc > CAP_C) Nc = CAP_C;
    if (Mc > CAP_C) Mc = CAP_C;

    zero_kernel<<<(FLAGS_TOTAL + 255) / 256, 256>>>();

    int tot = Nf + Mf + Nc + Mc;
    prep_kernel<<<(tot + 255) / 256, 256>>>(rf, Nf, sf, Mf, rc, Nc, sc, Mc, T);

    // fine: p2p (thr = 0.1)
    {
        int qb = (imax_(Nf, Mf) + THREADS * RQ - 1) / (THREADS * RQ);
        int zb = (imax_(Nf, Mf) + TILE - 1) / TILE;
        dim3 g(qb, 2, zb);
        flag_kernel<0><<<g, THREADS>>>(Nf, Mf, Mf, Nf, 0.5f * 0.1f * 0.1f);
    }
    // coarse: n2p (thr = 0.5)
    {
        int qb = (imax_(Nc, Mc) + THREADS * RQ - 1) / (THREADS * RQ);
        int zb = (imax_(Nf, Mf) + TILE - 1) / TILE;
        dim3 g(qb, 2, zb);
        flag_kernel<1><<<g, THREADS>>>(Nc, Mc, Mf, Nf, 0.5f * 0.5f * 0.5f);
    }

    int nmax = imax_(Nf + Mf, Nc + Mc);
    reduce_kernel<<<(nmax + 255) / 256, 256>>>(p2p_ref, p2p_src, n2p_ref, n2p_src,
                                               Nf, Mf, Nc, Mc);

    finalize_kernel<<<1, 32>>>(out, Nf + Mf, Nc + Mc);
}

// round 2
// speedup vs baseline: 1.8175x; 1.8175x over previous
#include <cuda_runtime.h>

// ---------------- configuration ----------------
#define THREADS 128
#define TILE    512          // database points per CTA tile (coarse brute force)
#define RQC     2            // queries per thread (coarse)

#define CAP_F 16384
#define CAP_C 2048

// spatial grid for fine pass
#define GRID_DIM  64
#define NCELLS    (GRID_DIM*GRID_DIM*GRID_DIM)   // 262144
#define CELL      0.1875f
#define INV_CELL  5.33333333f
#define ORG       (-6.0f)
#define KB        32         // bucket capacity

// flag array sections
#define F_REFF   0
#define F_SRCFT  16384
#define F_REFC   32768
#define F_SRCCT  34816
#define FLAGS_TOTAL 36864

typedef unsigned long long ull;

// ---------------- device scratch (no runtime allocation allowed) ----------------
__device__ float4 g_reff [CAP_F];   // ref_points_f       (x,y,z, -0.5*|p|^2)
__device__ float4 g_srcft[CAP_F];   // transformed src_f  (x,y,z, -0.5*|p|^2)
__device__ float4 g_refc [CAP_C];
__device__ float4 g_srcct[CAP_C];
__device__ int    g_flags[FLAGS_TOTAL];
__device__ float  g_acc[8];
__device__ int    g_counts[NCELLS];
__device__ int    g_bucket[NCELLS * KB];    // 33.5 MB static

// ---------------- packed f32x2 helpers ----------------
__device__ __forceinline__ ull pack2(float a, float b) {
    ull r; asm("mov.b64 %0, {%1,%2};" : "=l"(r) : "f"(a), "f"(b)); return r;
}
__device__ __forceinline__ void unpack2(ull v, float& a, float& b) {
    asm("mov.b64 {%0,%1}, %2;" : "=f"(a), "=f"(b) : "l"(v));
}
__device__ __forceinline__ ull fma2(ull a, ull b, ull c) {
    ull d; asm("fma.rn.f32x2 %0, %1, %2, %3;" : "=l"(d) : "l"(a), "l"(b), "l"(c));
    return d;
}

__device__ __forceinline__ int cell_coord(float v) {
    int i = (int)floorf((v - ORG) * INV_CELL);
    return min(GRID_DIM - 1, max(0, i));
}

// ---------------- setup: zero scratch + transform + h = -0.5|p|^2 ----------------
__global__ void setup_kernel(const float* __restrict__ rf, int Nf,
                             const float* __restrict__ sf, int Mf,
                             const float* __restrict__ rc, int Nc,
                             const float* __restrict__ sc, int Mc,
                             const float* __restrict__ T) {
    int i = blockIdx.x * blockDim.x + threadIdx.x;
    if (i < NCELLS)      g_counts[i] = 0;
    if (i < FLAGS_TOTAL) g_flags[i]  = 0;
    if (i < 8)           g_acc[i]    = 0.0f;

    if (i < Nf) {
        float x = rf[3*i], y = rf[3*i+1], z = rf[3*i+2];
        g_reff[i] = make_float4(x, y, z, -0.5f*(x*x + y*y + z*z));
    } else if (i < Nf + Mf) {
        int j = i - Nf;
        float px = sf[3*j], py = sf[3*j+1], pz = sf[3*j+2];
        float x = T[0]*px + T[1]*py + T[2]*pz  + T[3];
        float y = T[4]*px + T[5]*py + T[6]*pz  + T[7];
        float z = T[8]*px + T[9]*py + T[10]*pz + T[11];
        g_srcft[j] = make_float4(x, y, z, -0.5f*(x*x + y*y + z*z));
    } else if (i < Nf + Mf + Nc) {
        int j = i - Nf - Mf;
        float x = rc[3*j], y = rc[3*j+1], z = rc[3*j+2];
        g_refc[j] = make_float4(x, y, z, -0.5f*(x*x + y*y + z*z));
    } else if (i < Nf + Mf + Nc + Mc) {
        int j = i - Nf - Mf - Nc;
        float px = sc[3*j], py = sc[3*j+1], pz = sc[3*j+2];
        float x = T[0]*px + T[1]*py + T[2]*pz  + T[3];
        float y = T[4]*px + T[5]*py + T[6]*pz  + T[7];
        float z = T[8]*px + T[9]*py + T[10]*pz + T[11];
        g_srcct[j] = make_float4(x, y, z, -0.5f*(x*x + y*y + z*z));
    }
}

// ---------------- scatter transformed src_f into grid buckets ----------------
__global__ void scatter_kernel(int Mf) {
    int i = blockIdx.x * blockDim.x + threadIdx.x;
    if (i >= Mf) return;
    float4 s = g_srcft[i];
    int c = (cell_coord(s.z) * GRID_DIM + cell_coord(s.y)) * GRID_DIM + cell_coord(s.x);
    int slot = atomicAdd(&g_counts[c], 1);
    if (slot < KB) g_bucket[c * KB + slot] = i;
}

// ---------------- fine pass: symmetric pair marking via grid ----------------
// thread t handles query r = t/3, z-slab dz = t%3 - 1
__global__ __launch_bounds__(256)
void fine_query_kernel(int Nf, float halfthr2) {
    int t = blockIdx.x * blockDim.x + threadIdx.x;
    int r = t / 3;
    if (r >= Nf) return;
    int dz = t - 3*r - 1;

    float4 Q = g_reff[r];
    int cx = cell_coord(Q.x);
    int cy = cell_coord(Q.y);
    int cz = cell_coord(Q.z);
    int zz = cz + dz;
    if (zz < 0 || zz >= GRID_DIM) return;

    float ci = -Q.w - halfthr2;
    int hit = 0;

    int y0 = max(cy - 1, 0), y1 = min(cy + 1, GRID_DIM - 1);
    int x0 = max(cx - 1, 0), x1 = min(cx + 1, GRID_DIM - 1);
    for (int yy = y0; yy <= y1; yy++) {
        int crow = (zz * GRID_DIM + yy) * GRID_DIM;
        for (int xx = x0; xx <= x1; xx++) {
            int c = crow + xx;
            int cnt = min(g_counts[c], KB);
            int base = c * KB;
            for (int k = 0; k < cnt; k++) {
                int idx = g_bucket[base + k];
                float4 S = g_srcft[idx];
                float d = fmaf(Q.x, S.x, fmaf(Q.y, S.y, fmaf(Q.z, S.z, S.w)));
                if (d > ci) {
                    hit = 1;
                    g_flags[F_SRCFT + idx] = 1;   // benign race
                }
            }
        }
    }
    if (hit) g_flags[F_REFF + r] = 1;             // benign race across dz slabs
}

// ---------------- coarse pass: brute force, packed f32x2 ----------------
// job0: q=refc vs db=srcft ; job1: q=srcct vs db=reff
__global__ __launch_bounds__(THREADS)
void coarse_kernel(int nq0, int nq1, int ndb0, int ndb1, float halfthr2) {
    __shared__ ull sx[TILE/2], sy[TILE/2], sz[TILE/2], sw[TILE/2];

    int job = blockIdx.y;
    const float4* q  = job ? g_srcct : g_refc;
    const float4* db = job ? g_reff  : g_srcft;
    int* flags = g_flags + (job ? F_SRCCT : F_REFC);
    int nq  = job ? nq1  : nq0;
    int ndb = job ? ndb1 : ndb0;

    int t = threadIdx.x;
    int dbase = blockIdx.z * TILE;

    #pragma unroll
    for (int u = 0; u < 2; u++) {
        int slot = 2*t + u;
        int gi = dbase + 2*slot;
        float4 d0 = (gi     < ndb) ? db[gi]   : make_float4(0.f,0.f,0.f,-1e30f);
        float4 d1 = (gi + 1 < ndb) ? db[gi+1] : make_float4(0.f,0.f,0.f,-1e30f);
        sx[slot] = pack2(d0.x, d1.x);
        sy[slot] = pack2(d0.y, d1.y);
        sz[slot] = pack2(d0.z, d1.z);
        sw[slot] = pack2(d0.w, d1.w);
    }

    int qbase = blockIdx.x * (THREADS * RQC);
    ull  qx2[RQC], qy2[RQC], qz2[RQC];
    float c[RQC], mlo[RQC], mhi[RQC];
    #pragma unroll
    for (int r = 0; r < RQC; r++) {
        int qi = qbase + r*THREADS + t;
        float4 Q = q[(qi < nq) ? qi : 0];
        qx2[r] = pack2(Q.x, Q.x);
        qy2[r] = pack2(Q.y, Q.y);
        qz2[r] = pack2(Q.z, Q.z);
        c[r]   = -Q.w - halfthr2;
        mlo[r] = -3e38f;
        mhi[r] = -3e38f;
    }
    __syncthreads();

    #pragma unroll 4
    for (int k = 0; k < TILE/2; k++) {
        ull yx = sx[k], yy = sy[k], yz = sz[k], yw = sw[k];
        #pragma unroll
        for (int r = 0; r < RQC; r++) {
            ull tt = fma2(qz2[r], yz, yw);
            tt     = fma2(qy2[r], yy, tt);
            tt     = fma2(qx2[r], yx, tt);
            float lo, hi; unpack2(tt, lo, hi);
            mlo[r] = fmaxf(mlo[r], lo);
            mhi[r] = fmaxf(mhi[r], hi);
        }
    }

    #pragma unroll
    for (int r = 0; r < RQC; r++) {
        int qi = qbase + r*THREADS + t;
        if (qi < nq && fmaxf(mlo[r], mhi[r]) > c[r]) flags[qi] = 1;
    }
}

// ---------------- reduce: accumulate (sum_gt, sum_pos_bce, sum_neg_bce) x2 ----------------
__global__ void reduce_kernel(const float* __restrict__ p2p_ref,
                              const float* __restrict__ p2p_src,
                              const float* __restrict__ n2p_ref,
                              const float* __restrict__ n2p_src,
                              int Nf, int Mf, int Nc, int Mc) {
    int i = blockIdx.x * blockDim.x + threadIdx.x;
    float v0 = 0.f, v1 = 0.f, v2 = 0.f, v3 = 0.f, v4 = 0.f, v5 = 0.f;

    if (i < Mf + Nf) {   // concat order: [src scores | ref scores]
        float pred; int gt;
        if (i < Mf) { pred = p2p_src[i];      gt = g_flags[F_SRCFT + i]; }
        else        { pred = p2p_ref[i - Mf]; gt = g_flags[F_REFF + (i - Mf)]; }
        float bce = gt ? -logf(pred) : -log1pf(-pred);
        v0 = (float)gt;
        v1 = gt ? bce : 0.f;
        v2 = gt ? 0.f : bce;
    }
    if (i < Mc + Nc) {
        float pred; int gt;
        if (i < Mc) { pred = n2p_src[i];      gt = g_flags[F_SRCCT + i]; }
        else        { pred = n2p_ref[i - Mc]; gt = g_flags[F_REFC + (i - Mc)]; }
        float bce = gt ? -logf(pred) : -log1pf(-pred);
        v3 = (float)gt;
        v4 = gt ? bce : 0.f;
        v5 = gt ? 0.f : bce;
    }

    #pragma unroll
    for (int off = 16; off; off >>= 1) {
        v0 += __shfl_down_sync(0xffffffffu, v0, off);
        v1 += __shfl_down_sync(0xffffffffu, v1, off);
        v2 += __shfl_down_sync(0xffffffffu, v2, off);
        v3 += __shfl_down_sync(0xffffffffu, v3, off);
        v4 += __shfl_down_sync(0xffffffffu, v4, off);
        v5 += __shfl_down_sync(0xffffffffu, v5, off);
    }
    if ((threadIdx.x & 31) == 0) {
        atomicAdd(&g_acc[0], v0);
        atomicAdd(&g_acc[1], v1);
        atomicAdd(&g_acc[2], v2);
        atomicAdd(&g_acc[3], v3);
        atomicAdd(&g_acc[4], v4);
        atomicAdd(&g_acc[5], v5);
    }
}

// ---------------- finalize ----------------
__global__ void finalize_kernel(float* out, int np2p, int nn2p) {
    if (threadIdx.x == 0 && blockIdx.x == 0) {
        float S1 = g_acc[0], Sp = g_acc[1], Sn = g_acc[2];
        float wneg = S1 / (float)np2p;
        float wpos = 1.0f - wneg;
        float p2p = (wpos * Sp + wneg * Sn) / (float)np2p;

        S1 = g_acc[3]; Sp = g_acc[4]; Sn = g_acc[5];
        float wneg2 = S1 / (float)nn2p;
        float wpos2 = 1.0f - wneg2;
        float n2p = (wpos2 * Sp + wneg2 * Sn) / (float)nn2p;

        out[0] = n2p;
        out[1] = p2p;
    }
}

static inline int imax_(int a, int b) { return a > b ? a : b; }

extern "C" void kernel_launch(void* const* d_in, const int* in_sizes, int n_in,
                              void* d_out, int out_size) {
    const float* rc = (const float*)d_in[0]; int Nc = in_sizes[0] / 3;
    const float* sc = (const float*)d_in[1]; int Mc = in_sizes[1] / 3;
    const float* rf = (const float*)d_in[2]; int Nf = in_sizes[2] / 3;
    const float* sf = (const float*)d_in[3]; int Mf = in_sizes[3] / 3;
    const float* T  = (const float*)d_in[4];
    const float* p2p_ref = (const float*)d_in[5];
    const float* p2p_src = (const float*)d_in[6];
    const float* n2p_ref = (const float*)d_in[7];
    const float* n2p_src = (const float*)d_in[8];
    float* out = (float*)d_out;

    if (Nf > CAP_F) Nf = CAP_F;
    if (Mf > CAP_F) Mf = CAP_F;
    if (Nc > CAP_C) Nc = CAP_C;
    if (Mc > CAP_C) Mc = CAP_C;

    // setup: zero counts/flags/acc + transform & precompute h
    setup_kernel<<<(NCELLS + 255) / 256, 256>>>(rf, Nf, sf, Mf, rc, Nc, sc, Mc, T);

    // build grid on transformed src_f
    scatter_kernel<<<(Mf + 255) / 256, 256>>>(Mf);

    // fine pass (p2p, thr=0.1): one symmetric sweep sets both flag arrays
    {
        int nthreads = Nf * 3;
        fine_query_kernel<<<(nthreads + 255) / 256, 256>>>(Nf, 0.5f * 0.1f * 0.1f);
    }

    // coarse pass (n2p, thr=0.5): brute force
    {
        int qb = (imax_(Nc, Mc) + THREADS * RQC - 1) / (THREADS * RQC);
        int zb = (imax_(Nf, Mf) + TILE - 1) / TILE;
        dim3 g(qb, 2, zb);
        coarse_kernel<<<g, THREADS>>>(Nc, Mc, Mf, Nf, 0.5f * 0.5f * 0.5f);
    }

    int nmax = imax_(Nf + Mf, Nc + Mc);
    reduce_kernel<<<(nmax + 255) / 256, 256>>>(p2p_ref, p2p_src, n2p_ref, n2p_src,
                                               Nf, Mf, Nc, Mc);

    finalize_kernel<<<1, 32>>>(out, Nf + Mf, Nc + Mc);
}

// round 3
// speedup vs baseline: 3.0655x; 1.6867x over previous
#include <cuda_runtime.h>

// ---------------- configuration ----------------
#define THREADS 128
#define TILE    256          // database points per CTA tile (coarse brute force)
#define RQC     2            // queries per thread (coarse)

#define CAP_F 16384
#define CAP_C 2048

// spatial grid for fine pass: cell >= thr so +/-1 cell neighborhood suffices
#define GRID_DIM  96
#define NCELLS    (GRID_DIM*GRID_DIM*GRID_DIM)   // 884736
#define INV_CELL  9.52380952f                     // 1/0.105
#define ORG       (-5.04f)                        // 96*0.105 = 10.08 span
#define KB        16                              // bucket capacity

// flag array sections
#define F_REFF   0
#define F_SRCFT  16384
#define F_REFC   32768
#define F_SRCCT  34816
#define FLAGS_TOTAL 36864

typedef unsigned long long ull;

// ---------------- device scratch (no runtime allocation allowed) ----------------
__device__ float4 g_reff [CAP_F];   // ref_points_f       (x,y,z, -0.5*|p|^2)
__device__ float4 g_srcft[CAP_F];   // transformed src_f  (x,y,z, -0.5*|p|^2)
__device__ float4 g_refc [CAP_C];
__device__ float4 g_srcct[CAP_C];
__device__ int    g_flags[FLAGS_TOTAL];
__device__ float  g_acc[8];
__device__ int    g_done;
__device__ int    g_counts[NCELLS];
__device__ int    g_bucket[NCELLS * KB];    // ~56.6 MB static

// ---------------- packed f32x2 helpers ----------------
__device__ __forceinline__ ull pack2(float a, float b) {
    ull r; asm("mov.b64 %0, {%1,%2};" : "=l"(r) : "f"(a), "f"(b)); return r;
}
__device__ __forceinline__ void unpack2(ull v, float& a, float& b) {
    asm("mov.b64 {%0,%1}, %2;" : "=f"(a), "=f"(b) : "l"(v));
}
__device__ __forceinline__ ull fma2(ull a, ull b, ull c) {
    ull d; asm("fma.rn.f32x2 %0, %1, %2, %3;" : "=l"(d) : "l"(a), "l"(b), "l"(c));
    return d;
}

__device__ __forceinline__ int cell_coord(float v) {
    int i = (int)floorf((v - ORG) * INV_CELL);
    return min(GRID_DIM - 1, max(0, i));
}

// ---------------- setup: zero scratch + transform + h = -0.5|p|^2 ----------------
__global__ void setup_kernel(const float* __restrict__ rf, int Nf,
                             const float* __restrict__ sf, int Mf,
                             const float* __restrict__ rc, int Nc,
                             const float* __restrict__ sc, int Mc,
                             const float* __restrict__ T) {
    int i = blockIdx.x * blockDim.x + threadIdx.x;
    if (i < NCELLS)      g_counts[i] = 0;
    if (i < FLAGS_TOTAL) g_flags[i]  = 0;
    if (i < 8)           g_acc[i]    = 0.0f;
    if (i == 0)          g_done      = 0;

    if (i < Nf) {
        float x = rf[3*i], y = rf[3*i+1], z = rf[3*i+2];
        g_reff[i] = make_float4(x, y, z, -0.5f*(x*x + y*y + z*z));
    } else if (i < Nf + Mf) {
        int j = i - Nf;
        float px = sf[3*j], py = sf[3*j+1], pz = sf[3*j+2];
        float x = T[0]*px + T[1]*py + T[2]*pz  + T[3];
        float y = T[4]*px + T[5]*py + T[6]*pz  + T[7];
        float z = T[8]*px + T[9]*py + T[10]*pz + T[11];
        g_srcft[j] = make_float4(x, y, z, -0.5f*(x*x + y*y + z*z));
    } else if (i < Nf + Mf + Nc) {
        int j = i - Nf - Mf;
        float x = rc[3*j], y = rc[3*j+1], z = rc[3*j+2];
        g_refc[j] = make_float4(x, y, z, -0.5f*(x*x + y*y + z*z));
    } else if (i < Nf + Mf + Nc + Mc) {
        int j = i - Nf - Mf - Nc;
        float px = sc[3*j], py = sc[3*j+1], pz = sc[3*j+2];
        float x = T[0]*px + T[1]*py + T[2]*pz  + T[3];
        float y = T[4]*px + T[5]*py + T[6]*pz  + T[7];
        float z = T[8]*px + T[9]*py + T[10]*pz + T[11];
        g_srcct[j] = make_float4(x, y, z, -0.5f*(x*x + y*y + z*z));
    }
}

// ---------------- scatter transformed src_f into grid buckets ----------------
__global__ void scatter_kernel(int Mf) {
    int i = blockIdx.x * blockDim.x + threadIdx.x;
    if (i >= Mf) return;
    float4 s = g_srcft[i];
    int c = (cell_coord(s.z) * GRID_DIM + cell_coord(s.y)) * GRID_DIM + cell_coord(s.x);
    int slot = atomicAdd(&g_counts[c], 1);
    if (slot < KB) g_bucket[c * KB + slot] = i;
}

// ---------------- fine pass: symmetric pair marking via grid ----------------
// 9 threads per query: thread handles slab (dz, dy), scans 3 x-cells
__global__ __launch_bounds__(256)
void fine_query_kernel(int Nf, float halfthr2) {
    int t = blockIdx.x * blockDim.x + threadIdx.x;
    int r = t / 9;
    if (r >= Nf) return;
    int s = t - 9*r;
    int dz = s / 3 - 1;
    int dy = s - 3*(s/3) - 1;

    float4 Q = g_reff[r];
    int cx = cell_coord(Q.x);
    int cy = cell_coord(Q.y);
    int cz = cell_coord(Q.z);
    int zz = cz + dz, yy = cy + dy;
    if (zz < 0 || zz >= GRID_DIM || yy < 0 || yy >= GRID_DIM) return;

    float ci = -Q.w - halfthr2;
    int x0 = max(cx - 1, 0), x1 = min(cx + 1, GRID_DIM - 1);
    int crow = (zz * GRID_DIM + yy) * GRID_DIM;

    // prefetch counts for up to 3 adjacent x-cells (contiguous in memory)
    int nxt = x1 - x0 + 1;
    int cnt0 = min(g_counts[crow + x0], KB);
    int cnt1 = (nxt > 1) ? min(g_counts[crow + x0 + 1], KB) : 0;
    int cnt2 = (nxt > 2) ? min(g_counts[crow + x0 + 2], KB) : 0;

    int hit = 0;
    #pragma unroll
    for (int xi = 0; xi < 3; xi++) {
        int cnt = (xi == 0) ? cnt0 : (xi == 1) ? cnt1 : cnt2;
        int base = (crow + x0 + xi) * KB;
        for (int k = 0; k < cnt; k++) {
            int idx = g_bucket[base + k];
            float4 S = g_srcft[idx];
            float d = fmaf(Q.x, S.x, fmaf(Q.y, S.y, fmaf(Q.z, S.z, S.w)));
            if (d > ci) {
                hit = 1;
                g_flags[F_SRCFT + idx] = 1;   // benign race
            }
        }
    }
    if (hit) g_flags[F_REFF + r] = 1;         // benign race across slabs
}

// ---------------- coarse pass: brute force, packed f32x2 ----------------
// job0: q=refc vs db=srcft ; job1: q=srcct vs db=reff
__global__ __launch_bounds__(THREADS)
void coarse_kernel(int nq0, int nq1, int ndb0, int ndb1, float halfthr2) {
    __shared__ ull sx[TILE/2], sy[TILE/2], sz[TILE/2], sw[TILE/2];

    int job = blockIdx.y;
    const float4* q  = job ? g_srcct : g_refc;
    const float4* db = job ? g_reff  : g_srcft;
    int* flags = g_flags + (job ? F_SRCCT : F_REFC);
    int nq  = job ? nq1  : nq0;
    int ndb = job ? ndb1 : ndb0;

    int t = threadIdx.x;
    int dbase = blockIdx.z * TILE;

    {   // TILE/2 = 128 slots, one per thread
        int slot = t;
        int gi = dbase + 2*slot;
        float4 d0 = (gi     < ndb) ? db[gi]   : make_float4(0.f,0.f,0.f,-1e30f);
        float4 d1 = (gi + 1 < ndb) ? db[gi+1] : make_float4(0.f,0.f,0.f,-1e30f);
        sx[slot] = pack2(d0.x, d1.x);
        sy[slot] = pack2(d0.y, d1.y);
        sz[slot] = pack2(d0.z, d1.z);
        sw[slot] = pack2(d0.w, d1.w);
    }

    int qbase = blockIdx.x * (THREADS * RQC);
    ull  qx2[RQC], qy2[RQC], qz2[RQC];
    float c[RQC], mlo[RQC], mhi[RQC];
    #pragma unroll
    for (int r = 0; r < RQC; r++) {
        int qi = qbase + r*THREADS + t;
        float4 Q = q[(qi < nq) ? qi : 0];
        qx2[r] = pack2(Q.x, Q.x);
        qy2[r] = pack2(Q.y, Q.y);
        qz2[r] = pack2(Q.z, Q.z);
        c[r]   = -Q.w - halfthr2;
        mlo[r] = -3e38f;
        mhi[r] = -3e38f;
    }
    __syncthreads();

    #pragma unroll 4
    for (int k = 0; k < TILE/2; k++) {
        ull yx = sx[k], yy = sy[k], yz = sz[k], yw = sw[k];
        #pragma unroll
        for (int r = 0; r < RQC; r++) {
            ull tt = fma2(qz2[r], yz, yw);
            tt     = fma2(qy2[r], yy, tt);
            tt     = fma2(qx2[r], yx, tt);
            float lo, hi; unpack2(tt, lo, hi);
            mlo[r] = fmaxf(mlo[r], lo);
            mhi[r] = fmaxf(mhi[r], hi);
        }
    }

    #pragma unroll
    for (int r = 0; r < RQC; r++) {
        int qi = qbase + r*THREADS + t;
        if (qi < nq && fmaxf(mlo[r], mhi[r]) > c[r]) flags[qi] = 1;
    }
}

// ---------------- reduce + fused finalize ----------------
__global__ void reduce_kernel(const float* __restrict__ p2p_ref,
                              const float* __restrict__ p2p_src,
                              const float* __restrict__ n2p_ref,
                              const float* __restrict__ n2p_src,
                              int Nf, int Mf, int Nc, int Mc,
                              float* __restrict__ out) {
    int i = blockIdx.x * blockDim.x + threadIdx.x;
    float v0 = 0.f, v1 = 0.f, v2 = 0.f, v3 = 0.f, v4 = 0.f, v5 = 0.f;

    if (i < Mf + Nf) {   // concat order: [src scores | ref scores]
        float pred; int gt;
        if (i < Mf) { pred = p2p_src[i];      gt = g_flags[F_SRCFT + i]; }
        else        { pred = p2p_ref[i - Mf]; gt = g_flags[F_REFF + (i - Mf)]; }
        float bce = gt ? -logf(pred) : -log1pf(-pred);
        v0 = (float)gt;
        v1 = gt ? bce : 0.f;
        v2 = gt ? 0.f : bce;
    }
    if (i < Mc + Nc) {
        float pred; int gt;
        if (i < Mc) { pred = n2p_src[i];      gt = g_flags[F_SRCCT + i]; }
        else        { pred = n2p_ref[i - Mc]; gt = g_flags[F_REFC + (i - Mc)]; }
        float bce = gt ? -logf(pred) : -log1pf(-pred);
        v3 = (float)gt;
        v4 = gt ? bce : 0.f;
        v5 = gt ? 0.f : bce;
    }

    #pragma unroll
    for (int off = 16; off; off >>= 1) {
        v0 += __shfl_down_sync(0xffffffffu, v0, off);
        v1 += __shfl_down_sync(0xffffffffu, v1, off);
        v2 += __shfl_down_sync(0xffffffffu, v2, off);
        v3 += __shfl_down_sync(0xffffffffu, v3, off);
        v4 += __shfl_down_sync(0xffffffffu, v4, off);
        v5 += __shfl_down_sync(0xffffffffu, v5, off);
    }
    if ((threadIdx.x & 31) == 0) {
        atomicAdd(&g_acc[0], v0);
        atomicAdd(&g_acc[1], v1);
        atomicAdd(&g_acc[2], v2);
        atomicAdd(&g_acc[3], v3);
        atomicAdd(&g_acc[4], v4);
        atomicAdd(&g_acc[5], v5);
    }

    // fused finalize: last block computes outputs
    __threadfence();
    __syncthreads();
    __shared__ int s_last;
    if (threadIdx.x == 0)
        s_last = (atomicAdd(&g_done, 1) == (int)gridDim.x - 1);
    __syncthreads();
    if (s_last && threadIdx.x == 0) {
        int np2p = Nf + Mf, nn2p = Nc + Mc;
        float S1 = g_acc[0], Sp = g_acc[1], Sn = g_acc[2];
        float wneg = S1 / (float)np2p;
        float p2p = ((1.0f - wneg) * Sp + wneg * Sn) / (float)np2p;

        S1 = g_acc[3]; Sp = g_acc[4]; Sn = g_acc[5];
        float wneg2 = S1 / (float)nn2p;
        float n2p = ((1.0f - wneg2) * Sp + wneg2 * Sn) / (float)nn2p;

        out[0] = n2p;
        out[1] = p2p;
    }
}

static inline int imax_(int a, int b) { return a > b ? a : b; }

extern "C" void kernel_launch(void* const* d_in, const int* in_sizes, int n_in,
                              void* d_out, int out_size) {
    const float* rc = (const float*)d_in[0]; int Nc = in_sizes[0] / 3;
    const float* sc = (const float*)d_in[1]; int Mc = in_sizes[1] / 3;
    const float* rf = (const float*)d_in[2]; int Nf = in_sizes[2] / 3;
    const float* sf = (const float*)d_in[3]; int Mf = in_sizes[3] / 3;
    const float* T  = (const float*)d_in[4];
    const float* p2p_ref = (const float*)d_in[5];
    const float* p2p_src = (const float*)d_in[6];
    const float* n2p_ref = (const float*)d_in[7];
    const float* n2p_src = (const float*)d_in[8];
    float* out = (float*)d_out;

    if (Nf > CAP_F) Nf = CAP_F;
    if (Mf > CAP_F) Mf = CAP_F;
    if (Nc > CAP_C) Nc = CAP_C;
    if (Mc > CAP_C) Mc = CAP_C;

    // setup: zero counts/flags/acc + transform & precompute h
    setup_kernel<<<(NCELLS + 255) / 256, 256>>>(rf, Nf, sf, Mf, rc, Nc, sc, Mc, T);

    // build grid on transformed src_f
    scatter_kernel<<<(Mf + 255) / 256, 256>>>(Mf);

    // fine pass (p2p, thr=0.1): one symmetric sweep sets both flag arrays
    {
        int nthreads = Nf * 9;
        fine_query_kernel<<<(nthreads + 255) / 256, 256>>>(Nf, 0.5f * 0.1f * 0.1f);
    }

    // coarse pass (n2p, thr=0.5): brute force
    {
        int qb = (imax_(Nc, Mc) + THREADS * RQC - 1) / (THREADS * RQC);
        int zb = (imax_(Nf, Mf) + TILE - 1) / TILE;
        dim3 g(qb, 2, zb);
        coarse_kernel<<<g, THREADS>>>(Nc, Mc, Mf, Nf, 0.5f * 0.5f * 0.5f);
    }

    int nmax = imax_(Nf + Mf, Nc + Mc);
    reduce_kernel<<<(nmax + 255) / 256, 256>>>(p2p_ref, p2p_src, n2p_ref, n2p_src,
                                               Nf, Mf, Nc, Mc, out);
}

// round 4
// speedup vs baseline: 3.2932x; 1.0743x over previous
#include <cuda_runtime.h>

// ---------------- configuration ----------------
#define THREADS 128
#define TILE    256          // database points per CTA tile (coarse brute force)

#define CAP_F 16384
#define CAP_C 2048

// spatial grid for fine pass: cell >= thr so +/-1 cell neighborhood suffices
#define GRID_DIM  96
#define NCELLS    (GRID_DIM*GRID_DIM*GRID_DIM)   // 884736
#define CELLF     0.105f
#define INV_CELL  9.52380952f                     // 1/0.105
#define ORG       (-5.04f)                        // 96*0.105 = 10.08 span
#define KB        16                              // bucket capacity

// flag array sections
#define F_REFF   0
#define F_SRCFT  16384
#define F_REFC   32768
#define F_SRCCT  34816
#define FLAGS_TOTAL 36864

typedef unsigned long long ull;

// ---------------- device scratch (no runtime allocation allowed) ----------------
__device__ float4 g_reff [CAP_F];   // ref_points_f       (x,y,z, -0.5*|p|^2)
__device__ float4 g_srcft[CAP_F];   // transformed src_f  (x,y,z, -0.5*|p|^2)
__device__ float4 g_refc [CAP_C];
__device__ float4 g_srcct[CAP_C];
__device__ int    g_flags[FLAGS_TOTAL];
__device__ float  g_acc[8];
__device__ int    g_done;
__device__ int    g_counts[NCELLS];
__device__ float4 g_bucketf[NCELLS * KB];   // point + idx directly in bucket (~226 MB static)

// ---------------- packed f32x2 helpers ----------------
__device__ __forceinline__ ull pack2(float a, float b) {
    ull r; asm("mov.b64 %0, {%1,%2};" : "=l"(r) : "f"(a), "f"(b)); return r;
}
__device__ __forceinline__ void unpack2(ull v, float& a, float& b) {
    asm("mov.b64 {%0,%1}, %2;" : "=f"(a), "=f"(b) : "l"(v));
}
__device__ __forceinline__ ull fma2(ull a, ull b, ull c) {
    ull d; asm("fma.rn.f32x2 %0, %1, %2, %3;" : "=l"(d) : "l"(a), "l"(b), "l"(c));
    return d;
}

__device__ __forceinline__ int cell_coord(float v) {
    int i = (int)floorf((v - ORG) * INV_CELL);
    return min(GRID_DIM - 1, max(0, i));
}

// ---------------- setup: zero scratch + transform + h = -0.5|p|^2 ----------------
__global__ void setup_kernel(const float* __restrict__ rf, int Nf,
                             const float* __restrict__ sf, int Mf,
                             const float* __restrict__ rc, int Nc,
                             const float* __restrict__ sc, int Mc,
                             const float* __restrict__ T) {
    int i = blockIdx.x * blockDim.x + threadIdx.x;
    if (i < NCELLS)      g_counts[i] = 0;
    if (i < FLAGS_TOTAL) g_flags[i]  = 0;
    if (i < 8)           g_acc[i]    = 0.0f;
    if (i == 0)          g_done      = 0;

    if (i < Nf) {
        float x = rf[3*i], y = rf[3*i+1], z = rf[3*i+2];
        g_reff[i] = make_float4(x, y, z, -0.5f*(x*x + y*y + z*z));
    } else if (i < Nf + Mf) {
        int j = i - Nf;
        float px = sf[3*j], py = sf[3*j+1], pz = sf[3*j+2];
        float x = T[0]*px + T[1]*py + T[2]*pz  + T[3];
        float y = T[4]*px + T[5]*py + T[6]*pz  + T[7];
        float z = T[8]*px + T[9]*py + T[10]*pz + T[11];
        g_srcft[j] = make_float4(x, y, z, -0.5f*(x*x + y*y + z*z));
    } else if (i < Nf + Mf + Nc) {
        int j = i - Nf - Mf;
        float x = rc[3*j], y = rc[3*j+1], z = rc[3*j+2];
        g_refc[j] = make_float4(x, y, z, -0.5f*(x*x + y*y + z*z));
    } else if (i < Nf + Mf + Nc + Mc) {
        int j = i - Nf - Mf - Nc;
        float px = sc[3*j], py = sc[3*j+1], pz = sc[3*j+2];
        float x = T[0]*px + T[1]*py + T[2]*pz  + T[3];
        float y = T[4]*px + T[5]*py + T[6]*pz  + T[7];
        float z = T[8]*px + T[9]*py + T[10]*pz + T[11];
        g_srcct[j] = make_float4(x, y, z, -0.5f*(x*x + y*y + z*z));
    }
}

// ---------------- scatter transformed src_f into grid buckets (point stored inline) ----------------
__global__ void scatter_kernel(int Mf) {
    int i = blockIdx.x * blockDim.x + threadIdx.x;
    if (i >= Mf) return;
    float4 s = g_srcft[i];
    int c = (cell_coord(s.z) * GRID_DIM + cell_coord(s.y)) * GRID_DIM + cell_coord(s.x);
    int slot = atomicAdd(&g_counts[c], 1);
    if (slot < KB) g_bucketf[c * KB + slot] = make_float4(s.x, s.y, s.z, __int_as_float(i));
}

// ---------------- fat kernel: coarse brute force CTAs + fine grid-query CTAs ----------------
// coarse blocks [0, nCoarse): job = b%2 (0: q=refc vs srcft, 1: q=srcct vs reff)
// fine   blocks [nCoarse, ..): 9 threads/query, slab (dz,dy), 3 x-cells with box pruning
__global__ __launch_bounds__(THREADS)
void fat_kernel(int Nc, int Mc, int Nf, int Mf,
                int qb, int zb, int nCoarse,
                float halfthr2_c, float halfthr2_f, float thr2m_f) {
    __shared__ ull sx[TILE/2], sy[TILE/2], sz[TILE/2], sw[TILE/2];

    int b = blockIdx.x;
    int t = threadIdx.x;

    if (b < nCoarse) {
        // ---------------- coarse branch ----------------
        int job  = b & 1;
        int rem  = b >> 1;
        int qblk = rem % qb;
        int zblk = rem / qb;

        const float4* q  = job ? g_srcct : g_refc;
        const float4* db = job ? g_reff  : g_srcft;
        int* flags = g_flags + (job ? F_SRCCT : F_REFC);
        int nq  = job ? Mc : Nc;
        int ndb = job ? Nf : Mf;

        int dbase = zblk * TILE;
        {   // TILE/2 = 128 slots, one per thread
            int gi = dbase + 2*t;
            float4 d0 = (gi     < ndb) ? db[gi]   : make_float4(0.f,0.f,0.f,-1e30f);
            float4 d1 = (gi + 1 < ndb) ? db[gi+1] : make_float4(0.f,0.f,0.f,-1e30f);
            sx[t] = pack2(d0.x, d1.x);
            sy[t] = pack2(d0.y, d1.y);
            sz[t] = pack2(d0.z, d1.z);
            sw[t] = pack2(d0.w, d1.w);
        }

        int qi = qblk * THREADS + t;
        float4 Q = q[(qi < nq) ? qi : 0];
        ull qx2 = pack2(Q.x, Q.x);
        ull qy2 = pack2(Q.y, Q.y);
        ull qz2 = pack2(Q.z, Q.z);
        float ci = -Q.w - halfthr2_c;
        float mlo = -3e38f, mhi = -3e38f;
        __syncthreads();

        #pragma unroll 8
        for (int k = 0; k < TILE/2; k++) {
            ull tt = fma2(qz2, sz[k], sw[k]);
            tt     = fma2(qy2, sy[k], tt);
            tt     = fma2(qx2, sx[k], tt);
            float lo, hi; unpack2(tt, lo, hi);
            mlo = fmaxf(mlo, lo);
            mhi = fmaxf(mhi, hi);
        }
        if (qi < nq && fmaxf(mlo, mhi) > ci) flags[qi] = 1;
    } else {
        // ---------------- fine branch ----------------
        int gt = (b - nCoarse) * THREADS + t;
        int r = gt / 9;
        if (r >= Nf) return;
        int s = gt - 9*r;
        int dz = s / 3 - 1;
        int dy = s - 3*(s/3) - 1;

        float4 Q = g_reff[r];
        int cx = cell_coord(Q.x);
        int cy = cell_coord(Q.y);
        int cz = cell_coord(Q.z);
        int zz = cz + dz, yy = cy + dy;
        if (zz < 0 || zz >= GRID_DIM || yy < 0 || yy >= GRID_DIM) return;

        // box-distance pruning for the (dz,dy) slab
        float blz = ORG + zz * CELLF;
        float bly = ORG + yy * CELLF;
        float ddz = fmaxf(fmaxf(blz - Q.z, Q.z - (blz + CELLF)), 0.0f);
        float ddy = fmaxf(fmaxf(bly - Q.y, Q.y - (bly + CELLF)), 0.0f);
        float base2 = ddz*ddz + ddy*ddy;
        if (base2 > thr2m_f) return;

        float ci = -Q.w - halfthr2_f;
        int x0 = max(cx - 1, 0), x1 = min(cx + 1, GRID_DIM - 1);
        int crow = (zz * GRID_DIM + yy) * GRID_DIM;

        int hit = 0;
        for (int xx = x0; xx <= x1; xx++) {
            float blx = ORG + xx * CELLF;
            float ddx = fmaxf(fmaxf(blx - Q.x, Q.x - (blx + CELLF)), 0.0f);
            if (fmaf(ddx, ddx, base2) > thr2m_f) continue;

            int c = crow + xx;
            int cnt = min(g_counts[c], KB);
            int base = c * KB;
            for (int k = 0; k < cnt; k++) {
                float4 S = g_bucketf[base + k];
                float dot = fmaf(Q.x, S.x, fmaf(Q.y, S.y, Q.z * S.z));
                float sq  = fmaf(S.x, S.x, fmaf(S.y, S.y, S.z * S.z));
                if (fmaf(-0.5f, sq, dot) > ci) {
                    hit = 1;
                    g_flags[F_SRCFT + __float_as_int(S.w)] = 1;   // benign race
                }
            }
        }
        if (hit) g_flags[F_REFF + r] = 1;                         // benign race across slabs
    }
}

// ---------------- reduce + fused finalize ----------------
__global__ void reduce_kernel(const float* __restrict__ p2p_ref,
                              const float* __restrict__ p2p_src,
                              const float* __restrict__ n2p_ref,
                              const float* __restrict__ n2p_src,
                              int Nf, int Mf, int Nc, int Mc,
                              float* __restrict__ out) {
    int i = blockIdx.x * blockDim.x + threadIdx.x;
    float v0 = 0.f, v1 = 0.f, v2 = 0.f, v3 = 0.f, v4 = 0.f, v5 = 0.f;

    if (i < Mf + Nf) {   // concat order: [src scores | ref scores]
        float pred; int gt;
        if (i < Mf) { pred = p2p_src[i];      gt = g_flags[F_SRCFT + i]; }
        else        { pred = p2p_ref[i - Mf]; gt = g_flags[F_REFF + (i - Mf)]; }
        float bce = gt ? -logf(pred) : -log1pf(-pred);
        v0 = (float)gt;
        v1 = gt ? bce : 0.f;
        v2 = gt ? 0.f : bce;
    }
    if (i < Mc + Nc) {
        float pred; int gt;
        if (i < Mc) { pred = n2p_src[i];      gt = g_flags[F_SRCCT + i]; }
        else        { pred = n2p_ref[i - Mc]; gt = g_flags[F_REFC + (i - Mc)]; }
        float bce = gt ? -logf(pred) : -log1pf(-pred);
        v3 = (float)gt;
        v4 = gt ? bce : 0.f;
        v5 = gt ? 0.f : bce;
    }

    #pragma unroll
    for (int off = 16; off; off >>= 1) {
        v0 += __shfl_down_sync(0xffffffffu, v0, off);
        v1 += __shfl_down_sync(0xffffffffu, v1, off);
        v2 += __shfl_down_sync(0xffffffffu, v2, off);
        v3 += __shfl_down_sync(0xffffffffu, v3, off);
        v4 += __shfl_down_sync(0xffffffffu, v4, off);
        v5 += __shfl_down_sync(0xffffffffu, v5, off);
    }
    if ((threadIdx.x & 31) == 0) {
        atomicAdd(&g_acc[0], v0);
        atomicAdd(&g_acc[1], v1);
        atomicAdd(&g_acc[2], v2);
        atomicAdd(&g_acc[3], v3);
        atomicAdd(&g_acc[4], v4);
        atomicAdd(&g_acc[5], v5);
    }

    // fused finalize: last block computes outputs
    __threadfence();
    __syncthreads();
    __shared__ int s_last;
    if (threadIdx.x == 0)
        s_last = (atomicAdd(&g_done, 1) == (int)gridDim.x - 1);
    __syncthreads();
    if (s_last && threadIdx.x == 0) {
        int np2p = Nf + Mf, nn2p = Nc + Mc;
        float S1 = g_acc[0], Sp = g_acc[1], Sn = g_acc[2];
        float wneg = S1 / (float)np2p;
        float p2p = ((1.0f - wneg) * Sp + wneg * Sn) / (float)np2p;

        S1 = g_acc[3]; Sp = g_acc[4]; Sn = g_acc[5];
        float wneg2 = S1 / (float)nn2p;
        float n2p = ((1.0f - wneg2) * Sp + wneg2 * Sn) / (float)nn2p;

        out[0] = n2p;
        out[1] = p2p;
    }
}

static inline int imax_(int a, int b) { return a > b ? a : b; }

extern "C" void kernel_launch(void* const* d_in, const int* in_sizes, int n_in,
                              void* d_out, int out_size) {
    const float* rc = (const float*)d_in[0]; int Nc = in_sizes[0] / 3;
    const float* sc = (const float*)d_in[1]; int Mc = in_sizes[1] / 3;
    const float* rf = (const float*)d_in[2]; int Nf = in_sizes[2] / 3;
    const float* sf = (const float*)d_in[3]; int Mf = in_sizes[3] / 3;
    const float* T  = (const float*)d_in[4];
    const float* p2p_ref = (const float*)d_in[5];
    const float* p2p_src = (const float*)d_in[6];
    const float* n2p_ref = (const float*)d_in[7];
    const float* n2p_src = (const float*)d_in[8];
    float* out = (float*)d_out;

    if (Nf > CAP_F) Nf = CAP_F;
    if (Mf > CAP_F) Mf = CAP_F;
    if (Nc > CAP_C) Nc = CAP_C;
    if (Mc > CAP_C) Mc = CAP_C;

    // setup: zero counts/flags/acc + transform & precompute h
    setup_kernel<<<(NCELLS + 255) / 256, 256>>>(rf, Nf, sf, Mf, rc, Nc, sc, Mc, T);

    // build grid on transformed src_f
    scatter_kernel<<<(Mf + 255) / 256, 256>>>(Mf);

    // fat kernel: coarse (n2p, thr=0.5) + fine (p2p, thr=0.1)
    {
        int qb = (imax_(Nc, Mc) + THREADS - 1) / THREADS;
        int zb = (imax_(Nf, Mf) + TILE - 1) / TILE;
        int nCoarse = qb * zb * 2;
        int nFine = (Nf * 9 + THREADS - 1) / THREADS;
        fat_kernel<<<nCoarse + nFine, THREADS>>>(
            Nc, Mc, Nf, Mf, qb, zb, nCoarse,
            0.5f * 0.5f * 0.5f,          // coarse: 0.5*thr^2, thr=0.5
            0.5f * 0.1f * 0.1f,          // fine:   0.5*thr^2, thr=0.1
            0.1f * 0.1f * 1.0002f);      // fine box-prune threshold with margin
    }

    int nmax = imax_(Nf + Mf, Nc + Mc);
    reduce_kernel<<<(nmax + 255) / 256, 256>>>(p2p_ref, p2p_src, n2p_ref, n2p_src,
                                               Nf, Mf, Nc, Mc, out);
}

// round 5
// speedup vs baseline: 3.5170x; 1.0680x over previous
#include <cuda_runtime.h>

// ---------------- configuration ----------------
#define THREADS 128
#define TILE    256          // database points per CTA tile (coarse brute force)

#define CAP_F 16384
#define CAP_C 2048

// spatial grid for fine pass: cell >= thr so +/-1 cell neighborhood suffices
#define GRID_DIM  96
#define NCELLS    (GRID_DIM*GRID_DIM*GRID_DIM)   // 884736
#define CELLF     0.105f
#define INV_CELL  9.52380952f                     // 1/0.105
#define ORG       (-5.04f)                        // 96*0.105 = 10.08 span
#define KB        16                              // bucket capacity

// flag array sections
#define F_REFF   0
#define F_SRCFT  16384
#define F_REFC   32768
#define F_SRCCT  34816
#define FLAGS_TOTAL 36864

typedef unsigned long long ull;

// ---------------- device scratch (all .bss zero-init; every call self-cleans) ----------------
__device__ float4 g_reff [CAP_F];   // ref_points_f       (x,y,z, -0.5*|p|^2)
__device__ float4 g_srcft[CAP_F];   // transformed src_f  (x,y,z, -0.5*|p|^2)
__device__ float4 g_refc [CAP_C];
__device__ float4 g_srcct[CAP_C];
__device__ int    g_flags[FLAGS_TOTAL];   // zeroed by reduce after reading
__device__ float  g_acc[8];               // reset by last reduce block
__device__ int    g_done;                 // reset by last reduce block
__device__ int    g_counts[NCELLS];       // zeroed by reduce via touched cells
__device__ float4 g_bucketf[NCELLS * KB]; // point + idx inline (~226 MB static)

// ---------------- packed f32x2 helpers ----------------
__device__ __forceinline__ ull pack2(float a, float b) {
    ull r; asm("mov.b64 %0, {%1,%2};" : "=l"(r) : "f"(a), "f"(b)); return r;
}
__device__ __forceinline__ void unpack2(ull v, float& a, float& b) {
    asm("mov.b64 {%0,%1}, %2;" : "=f"(a), "=f"(b) : "l"(v));
}
__device__ __forceinline__ ull fma2(ull a, ull b, ull c) {
    ull d; asm("fma.rn.f32x2 %0, %1, %2, %3;" : "=l"(d) : "l"(a), "l"(b), "l"(c));
    return d;
}

__device__ __forceinline__ int cell_coord(float v) {
    int i = (int)floorf((v - ORG) * INV_CELL);
    return min(GRID_DIM - 1, max(0, i));
}
__device__ __forceinline__ int cell_of(float4 s) {
    return (cell_coord(s.z) * GRID_DIM + cell_coord(s.y)) * GRID_DIM + cell_coord(s.x);
}

// ---------------- setup: transform + h = -0.5|p|^2 + scatter (counts pre-zeroed) ----------------
__global__ void setup_kernel(const float* __restrict__ rf, int Nf,
                             const float* __restrict__ sf, int Mf,
                             const float* __restrict__ rc, int Nc,
                             const float* __restrict__ sc, int Mc,
                             const float* __restrict__ T) {
    int i = blockIdx.x * blockDim.x + threadIdx.x;
    if (i < Nf) {
        float x = rf[3*i], y = rf[3*i+1], z = rf[3*i+2];
        g_reff[i] = make_float4(x, y, z, -0.5f*(x*x + y*y + z*z));
    } else if (i < Nf + Mf) {
        int j = i - Nf;
        float px = sf[3*j], py = sf[3*j+1], pz = sf[3*j+2];
        float x = T[0]*px + T[1]*py + T[2]*pz  + T[3];
        float y = T[4]*px + T[5]*py + T[6]*pz  + T[7];
        float z = T[8]*px + T[9]*py + T[10]*pz + T[11];
        float4 s = make_float4(x, y, z, -0.5f*(x*x + y*y + z*z));
        g_srcft[j] = s;
        int c = cell_of(s);
        int slot = atomicAdd(&g_counts[c], 1);
        if (slot < KB) g_bucketf[c * KB + slot] = make_float4(x, y, z, __int_as_float(j));
    } else if (i < Nf + Mf + Nc) {
        int j = i - Nf - Mf;
        float x = rc[3*j], y = rc[3*j+1], z = rc[3*j+2];
        g_refc[j] = make_float4(x, y, z, -0.5f*(x*x + y*y + z*z));
    } else if (i < Nf + Mf + Nc + Mc) {
        int j = i - Nf - Mf - Nc;
        float px = sc[3*j], py = sc[3*j+1], pz = sc[3*j+2];
        float x = T[0]*px + T[1]*py + T[2]*pz  + T[3];
        float y = T[4]*px + T[5]*py + T[6]*pz  + T[7];
        float z = T[8]*px + T[9]*py + T[10]*pz + T[11];
        g_srcct[j] = make_float4(x, y, z, -0.5f*(x*x + y*y + z*z));
    }
}

// ---------------- fat kernel: coarse brute force CTAs + fine grid-query CTAs ----------------
__global__ __launch_bounds__(THREADS)
void fat_kernel(int Nc, int Mc, int Nf, int Mf,
                int qb, int zb, int nCoarse,
                float halfthr2_c, float halfthr2_f, float thr2m_f) {
    __shared__ ull sx[TILE/2], sy[TILE/2], sz[TILE/2], sw[TILE/2];

    int b = blockIdx.x;
    int t = threadIdx.x;

    if (b < nCoarse) {
        // ---------------- coarse branch ----------------
        int job  = b & 1;
        int rem  = b >> 1;
        int qblk = rem % qb;
        int zblk = rem / qb;

        const float4* q  = job ? g_srcct : g_refc;
        const float4* db = job ? g_reff  : g_srcft;
        int* flags = g_flags + (job ? F_SRCCT : F_REFC);
        int nq  = job ? Mc : Nc;
        int ndb = job ? Nf : Mf;

        int dbase = zblk * TILE;
        {   // TILE/2 = 128 slots, one per thread
            int gi = dbase + 2*t;
            float4 d0 = (gi     < ndb) ? db[gi]   : make_float4(0.f,0.f,0.f,-1e30f);
            float4 d1 = (gi + 1 < ndb) ? db[gi+1] : make_float4(0.f,0.f,0.f,-1e30f);
            sx[t] = pack2(d0.x, d1.x);
            sy[t] = pack2(d0.y, d1.y);
            sz[t] = pack2(d0.z, d1.z);
            sw[t] = pack2(d0.w, d1.w);
        }

        int qi = qblk * THREADS + t;
        float4 Q = q[(qi < nq) ? qi : 0];
        ull qx2 = pack2(Q.x, Q.x);
        ull qy2 = pack2(Q.y, Q.y);
        ull qz2 = pack2(Q.z, Q.z);
        float ci = -Q.w - halfthr2_c;
        float mlo = -3e38f, mhi = -3e38f;
        __syncthreads();

        #pragma unroll 8
        for (int k = 0; k < TILE/2; k++) {
            ull tt = fma2(qz2, sz[k], sw[k]);
            tt     = fma2(qy2, sy[k], tt);
            tt     = fma2(qx2, sx[k], tt);
            float lo, hi; unpack2(tt, lo, hi);
            mlo = fmaxf(mlo, lo);
            mhi = fmaxf(mhi, hi);
        }
        if (qi < nq && fmaxf(mlo, mhi) > ci) flags[qi] = 1;
    } else {
        // ---------------- fine branch: 9 threads/query, slab (dz,dy), 3 x-cells ----------------
        int gt = (b - nCoarse) * THREADS + t;
        int r = gt / 9;
        if (r >= Nf) return;
        int s = gt - 9*r;
        int dz = s / 3 - 1;
        int dy = s - 3*(s/3) - 1;

        float4 Q = g_reff[r];
        int cx = cell_coord(Q.x);
        int cy = cell_coord(Q.y);
        int cz = cell_coord(Q.z);
        int zz = cz + dz, yy = cy + dy;
        if (zz < 0 || zz >= GRID_DIM || yy < 0 || yy >= GRID_DIM) return;

        // box-distance pruning for the (dz,dy) slab
        float blz = ORG + zz * CELLF;
        float bly = ORG + yy * CELLF;
        float ddz = fmaxf(fmaxf(blz - Q.z, Q.z - (blz + CELLF)), 0.0f);
        float ddy = fmaxf(fmaxf(bly - Q.y, Q.y - (bly + CELLF)), 0.0f);
        float base2 = ddz*ddz + ddy*ddy;
        if (base2 > thr2m_f) return;

        float ci = -Q.w - halfthr2_f;
        int x0 = max(cx - 1, 0), x1 = min(cx + 1, GRID_DIM - 1);
        int crow = (zz * GRID_DIM + yy) * GRID_DIM;

        int hit = 0;
        for (int xx = x0; xx <= x1; xx++) {
            float blx = ORG + xx * CELLF;
            float ddx = fmaxf(fmaxf(blx - Q.x, Q.x - (blx + CELLF)), 0.0f);
            if (fmaf(ddx, ddx, base2) > thr2m_f) continue;

            int c = crow + xx;
            int cnt = min(g_counts[c], KB);
            int base = c * KB;
            for (int k = 0; k < cnt; k++) {
                float4 S = g_bucketf[base + k];
                float dot = fmaf(Q.x, S.x, fmaf(Q.y, S.y, Q.z * S.z));
                float sq  = fmaf(S.x, S.x, fmaf(S.y, S.y, S.z * S.z));
                if (fmaf(-0.5f, sq, dot) > ci) {
                    hit = 1;
                    g_flags[F_SRCFT + __float_as_int(S.w)] = 1;   // benign race
                }
            }
        }
        if (hit) g_flags[F_REFF + r] = 1;                         // benign race across slabs
    }
}

// ---------------- reduce + fused finalize + state cleanup ----------------
__global__ void reduce_kernel(const float* __restrict__ p2p_ref,
                              const float* __restrict__ p2p_src,
                              const float* __restrict__ n2p_ref,
                              const float* __restrict__ n2p_src,
                              int Nf, int Mf, int Nc, int Mc,
                              float* __restrict__ out) {
    int i = blockIdx.x * blockDim.x + threadIdx.x;
    float v0 = 0.f, v1 = 0.f, v2 = 0.f, v3 = 0.f, v4 = 0.f, v5 = 0.f;

    if (i < Mf + Nf) {   // concat order: [src scores | ref scores]
        float pred; int gt; int fidx;
        if (i < Mf) { pred = p2p_src[i];      fidx = F_SRCFT + i; }
        else        { pred = p2p_ref[i - Mf]; fidx = F_REFF + (i - Mf); }
        gt = g_flags[fidx];
        g_flags[fidx] = 0;                       // self-clean
        float bce = gt ? -logf(pred) : -log1pf(-pred);
        v0 = (float)gt;
        v1 = gt ? bce : 0.f;
        v2 = gt ? 0.f : bce;
    }
    if (i < Mc + Nc) {
        float pred; int gt; int fidx;
        if (i < Mc) { pred = n2p_src[i];      fidx = F_SRCCT + i; }
        else        { pred = n2p_ref[i - Mc]; fidx = F_REFC + (i - Mc); }
        gt = g_flags[fidx];
        g_flags[fidx] = 0;                       // self-clean
        float bce = gt ? -logf(pred) : -log1pf(-pred);
        v3 = (float)gt;
        v4 = gt ? bce : 0.f;
        v5 = gt ? 0.f : bce;
    }
    if (i < Mf) {
        g_counts[cell_of(g_srcft[i])] = 0;       // self-clean touched grid cells
    }

    #pragma unroll
    for (int off = 16; off; off >>= 1) {
        v0 += __shfl_down_sync(0xffffffffu, v0, off);
        v1 += __shfl_down_sync(0xffffffffu, v1, off);
        v2 += __shfl_down_sync(0xffffffffu, v2, off);
        v3 += __shfl_down_sync(0xffffffffu, v3, off);
        v4 += __shfl_down_sync(0xffffffffu, v4, off);
        v5 += __shfl_down_sync(0xffffffffu, v5, off);
    }
    if ((threadIdx.x & 31) == 0) {
        atomicAdd(&g_acc[0], v0);
        atomicAdd(&g_acc[1], v1);
        atomicAdd(&g_acc[2], v2);
        atomicAdd(&g_acc[3], v3);
        atomicAdd(&g_acc[4], v4);
        atomicAdd(&g_acc[5], v5);
        __threadfence();                         // fence by warp leaders only
    }
    __syncthreads();

    __shared__ int s_last;
    if (threadIdx.x == 0)
        s_last = (atomicAdd(&g_done, 1) == (int)gridDim.x - 1);
    __syncthreads();
    if (s_last && threadIdx.x == 0) {
        volatile float* acc = g_acc;
        int np2p = Nf + Mf, nn2p = Nc + Mc;
        float S1 = acc[0], Sp = acc[1], Sn = acc[2];
        float wneg = S1 / (float)np2p;
        float p2p = ((1.0f - wneg) * Sp + wneg * Sn) / (float)np2p;

        S1 = acc[3]; Sp = acc[4]; Sn = acc[5];
        float wneg2 = S1 / (float)nn2p;
        float n2p = ((1.0f - wneg2) * Sp + wneg2 * Sn) / (float)nn2p;

        out[0] = n2p;
        out[1] = p2p;

        // self-clean accumulators for the next replay
        g_acc[0] = 0.f; g_acc[1] = 0.f; g_acc[2] = 0.f;
        g_acc[3] = 0.f; g_acc[4] = 0.f; g_acc[5] = 0.f;
        g_done = 0;
    }
}

static inline int imax_(int a, int b) { return a > b ? a : b; }

extern "C" void kernel_launch(void* const* d_in, const int* in_sizes, int n_in,
                              void* d_out, int out_size) {
    const float* rc = (const float*)d_in[0]; int Nc = in_sizes[0] / 3;
    const float* sc = (const float*)d_in[1]; int Mc = in_sizes[1] / 3;
    const float* rf = (const float*)d_in[2]; int Nf = in_sizes[2] / 3;
    const float* sf = (const float*)d_in[3]; int Mf = in_sizes[3] / 3;
    const float* T  = (const float*)d_in[4];
    const float* p2p_ref = (const float*)d_in[5];
    const float* p2p_src = (const float*)d_in[6];
    const float* n2p_ref = (const float*)d_in[7];
    const float* n2p_src = (const float*)d_in[8];
    float* out = (float*)d_out;

    if (Nf > CAP_F) Nf = CAP_F;
    if (Mf > CAP_F) Mf = CAP_F;
    if (Nc > CAP_C) Nc = CAP_C;
    if (Mc > CAP_C) Mc = CAP_C;

    // setup: transform & precompute h + scatter into (pre-zeroed) grid
    int tot = Nf + Mf + Nc + Mc;
    setup_kernel<<<(tot + 255) / 256, 256>>>(rf, Nf, sf, Mf, rc, Nc, sc, Mc, T);

    // fat kernel: coarse (n2p, thr=0.5) + fine (p2p, thr=0.1)
    {
        int qb = (imax_(Nc, Mc) + THREADS - 1) / THREADS;
        int zb = (imax_(Nf, Mf) + TILE - 1) / TILE;
        int nCoarse = qb * zb * 2;
        int nFine = (Nf * 9 + THREADS - 1) / THREADS;
        fat_kernel<<<nCoarse + nFine, THREADS>>>(
            Nc, Mc, Nf, Mf, qb, zb, nCoarse,
            0.5f * 0.5f * 0.5f,          // coarse: 0.5*thr^2, thr=0.5
            0.5f * 0.1f * 0.1f,          // fine:   0.5*thr^2, thr=0.1
            0.1f * 0.1f * 1.0002f);      // fine box-prune threshold with margin
    }

    int nmax = imax_(Nf + Mf, Nc + Mc);
    reduce_kernel<<<(nmax + 255) / 256, 256>>>(p2p_ref, p2p_src, n2p_ref, n2p_src,
                                               Nf, Mf, Nc, Mc, out);
}

// round 6
// speedup vs baseline: 4.6974x; 1.3356x over previous
#include <cuda_runtime.h>

// ---------------- configuration ----------------
#define THREADS 128
#define TILE    256          // database points per CTA tile (coarse brute force)

#define CAP_F 16384
#define CAP_C 2048

// spatial grid for fine pass: cell >= thr so +/-1 cell neighborhood suffices
#define GRID_DIM  96
#define NCELLS    (GRID_DIM*GRID_DIM*GRID_DIM)   // 884736
#define CELLF     0.105f
#define INV_CELL  9.52380952f                     // 1/0.105
#define ORG       (-5.04f)                        // 96*0.105 = 10.08 span
#define KB        16                              // bucket capacity

// flag array sections
#define F_REFF   0
#define F_SRCFT  16384
#define F_REFC   32768
#define F_SRCCT  34816
#define FLAGS_TOTAL 36864

#define MAXPART 256          // max reduce blocks

typedef unsigned long long ull;

// ---------------- device scratch (all .bss zero-init; every call self-cleans) ----------------
__device__ float4 g_reff [CAP_F];   // ref_points_f       (x,y,z, -0.5*|p|^2)
__device__ float4 g_srcft[CAP_F];   // transformed src_f  (x,y,z, -0.5*|p|^2)
__device__ float4 g_refc [CAP_C];
__device__ float4 g_srcct[CAP_C];
__device__ int    g_flags[FLAGS_TOTAL];   // zeroed by reduce after reading
__device__ float  g_part[MAXPART][6];     // per-block partials (plain stores, no atomics)
__device__ int    g_done;                 // reset by last reduce block
__device__ int    g_counts[NCELLS];       // zeroed by reduce via touched cells
__device__ float4 g_bucketf[NCELLS * KB]; // point + idx inline (~226 MB static)

// ---------------- packed f32x2 helpers ----------------
__device__ __forceinline__ ull pack2(float a, float b) {
    ull r; asm("mov.b64 %0, {%1,%2};" : "=l"(r) : "f"(a), "f"(b)); return r;
}
__device__ __forceinline__ void unpack2(ull v, float& a, float& b) {
    asm("mov.b64 {%0,%1}, %2;" : "=f"(a), "=f"(b) : "l"(v));
}
__device__ __forceinline__ ull fma2(ull a, ull b, ull c) {
    ull d; asm("fma.rn.f32x2 %0, %1, %2, %3;" : "=l"(d) : "l"(a), "l"(b), "l"(c));
    return d;
}

__device__ __forceinline__ int cell_coord(float v) {
    int i = (int)floorf((v - ORG) * INV_CELL);
    return min(GRID_DIM - 1, max(0, i));
}
__device__ __forceinline__ int cell_of(float4 s) {
    return (cell_coord(s.z) * GRID_DIM + cell_coord(s.y)) * GRID_DIM + cell_coord(s.x);
}

// ---------------- setup: transform + h = -0.5|p|^2 + scatter (counts pre-zeroed) ----------------
__global__ void setup_kernel(const float* __restrict__ rf, int Nf,
                             const float* __restrict__ sf, int Mf,
                             const float* __restrict__ rc, int Nc,
                             const float* __restrict__ sc, int Mc,
                             const float* __restrict__ T) {
    int i = blockIdx.x * blockDim.x + threadIdx.x;
    if (i < Nf) {
        float x = rf[3*i], y = rf[3*i+1], z = rf[3*i+2];
        g_reff[i] = make_float4(x, y, z, -0.5f*(x*x + y*y + z*z));
    } else if (i < Nf + Mf) {
        int j = i - Nf;
        float px = sf[3*j], py = sf[3*j+1], pz = sf[3*j+2];
        float x = T[0]*px + T[1]*py + T[2]*pz  + T[3];
        float y = T[4]*px + T[5]*py + T[6]*pz  + T[7];
        float z = T[8]*px + T[9]*py + T[10]*pz + T[11];
        float4 s = make_float4(x, y, z, -0.5f*(x*x + y*y + z*z));
        g_srcft[j] = s;
        int c = cell_of(s);
        int slot = atomicAdd(&g_counts[c], 1);
        if (slot < KB) g_bucketf[c * KB + slot] = make_float4(x, y, z, __int_as_float(j));
    } else if (i < Nf + Mf + Nc) {
        int j = i - Nf - Mf;
        float x = rc[3*j], y = rc[3*j+1], z = rc[3*j+2];
        g_refc[j] = make_float4(x, y, z, -0.5f*(x*x + y*y + z*z));
    } else if (i < Nf + Mf + Nc + Mc) {
        int j = i - Nf - Mf - Nc;
        float px = sc[3*j], py = sc[3*j+1], pz = sc[3*j+2];
        float x = T[0]*px + T[1]*py + T[2]*pz  + T[3];
        float y = T[4]*px + T[5]*py + T[6]*pz  + T[7];
        float z = T[8]*px + T[9]*py + T[10]*pz + T[11];
        g_srcct[j] = make_float4(x, y, z, -0.5f*(x*x + y*y + z*z));
    }
}

// ---------------- fat kernel: coarse brute force CTAs + fine grid-query CTAs ----------------
__global__ __launch_bounds__(THREADS)
void fat_kernel(int Nc, int Mc, int Nf, int Mf,
                int qb, int zb, int nCoarse,
                float halfthr2_c, float halfthr2_f, float thr2m_f) {
    __shared__ ull sx[TILE/2], sy[TILE/2], sz[TILE/2], sw[TILE/2];

    int b = blockIdx.x;
    int t = threadIdx.x;

    if (b < nCoarse) {
        // ---------------- coarse branch ----------------
        int job  = b & 1;
        int rem  = b >> 1;
        int qblk = rem % qb;
        int zblk = rem / qb;

        const float4* q  = job ? g_srcct : g_refc;
        const float4* db = job ? g_reff  : g_srcft;
        int* flags = g_flags + (job ? F_SRCCT : F_REFC);
        int nq  = job ? Mc : Nc;
        int ndb = job ? Nf : Mf;

        int dbase = zblk * TILE;
        {   // TILE/2 = 128 slots, one per thread
            int gi = dbase + 2*t;
            float4 d0 = (gi     < ndb) ? db[gi]   : make_float4(0.f,0.f,0.f,-1e30f);
            float4 d1 = (gi + 1 < ndb) ? db[gi+1] : make_float4(0.f,0.f,0.f,-1e30f);
            sx[t] = pack2(d0.x, d1.x);
            sy[t] = pack2(d0.y, d1.y);
            sz[t] = pack2(d0.z, d1.z);
            sw[t] = pack2(d0.w, d1.w);
        }

        int qi = qblk * THREADS + t;
        float4 Q = q[(qi < nq) ? qi : 0];
        ull qx2 = pack2(Q.x, Q.x);
        ull qy2 = pack2(Q.y, Q.y);
        ull qz2 = pack2(Q.z, Q.z);
        float ci = -Q.w - halfthr2_c;
        float mlo = -3e38f, mhi = -3e38f;
        __syncthreads();

        #pragma unroll 8
        for (int k = 0; k < TILE/2; k++) {
            ull tt = fma2(qz2, sz[k], sw[k]);
            tt     = fma2(qy2, sy[k], tt);
            tt     = fma2(qx2, sx[k], tt);
            float lo, hi; unpack2(tt, lo, hi);
            mlo = fmaxf(mlo, lo);
            mhi = fmaxf(mhi, hi);
        }
        if (qi < nq && fmaxf(mlo, mhi) > ci) flags[qi] = 1;
    } else {
        // ---------------- fine branch: 9 threads/query, slab (dz,dy), 3 x-cells ----------------
        int gt = (b - nCoarse) * THREADS + t;
        int r = gt / 9;
        if (r >= Nf) return;
        int s = gt - 9*r;
        int dz = s / 3 - 1;
        int dy = s - 3*(s/3) - 1;

        float4 Q = g_reff[r];
        int cx = cell_coord(Q.x);
        int cy = cell_coord(Q.y);
        int cz = cell_coord(Q.z);
        int zz = cz + dz, yy = cy + dy;
        if (zz < 0 || zz >= GRID_DIM || yy < 0 || yy >= GRID_DIM) return;

        // box-distance pruning for the (dz,dy) slab
        float blz = ORG + zz * CELLF;
        float bly = ORG + yy * CELLF;
        float ddz = fmaxf(fmaxf(blz - Q.z, Q.z - (blz + CELLF)), 0.0f);
        float ddy = fmaxf(fmaxf(bly - Q.y, Q.y - (bly + CELLF)), 0.0f);
        float base2 = ddz*ddz + ddy*ddy;
        if (base2 > thr2m_f) return;

        float ci = -Q.w - halfthr2_f;
        int x0 = max(cx - 1, 0), x1 = min(cx + 1, GRID_DIM - 1);
        int crow = (zz * GRID_DIM + yy) * GRID_DIM;

        int hit = 0;
        for (int xx = x0; xx <= x1; xx++) {
            float blx = ORG + xx * CELLF;
            float ddx = fmaxf(fmaxf(blx - Q.x, Q.x - (blx + CELLF)), 0.0f);
            if (fmaf(ddx, ddx, base2) > thr2m_f) continue;

            int c = crow + xx;
            int cnt = min(g_counts[c], KB);
            int base = c * KB;
            for (int k = 0; k < cnt; k++) {
                float4 S = g_bucketf[base + k];
                float dot = fmaf(Q.x, S.x, fmaf(Q.y, S.y, Q.z * S.z));
                float sq  = fmaf(S.x, S.x, fmaf(S.y, S.y, S.z * S.z));
                if (fmaf(-0.5f, sq, dot) > ci) {
                    hit = 1;
                    g_flags[F_SRCFT + __float_as_int(S.w)] = 1;   // benign race
                }
            }
        }
        if (hit) g_flags[F_REFF + r] = 1;                         // benign race across slabs
    }
}

// ---------------- reduce: hierarchical (warp -> smem -> per-block partial slot) ----------------
__global__ __launch_bounds__(256)
void reduce_kernel(const float* __restrict__ p2p_ref,
                   const float* __restrict__ p2p_src,
                   const float* __restrict__ n2p_ref,
                   const float* __restrict__ n2p_src,
                   int Nf, int Mf, int Nc, int Mc,
                   float* __restrict__ out) {
    __shared__ float s_red[8][6];
    __shared__ int s_last;

    int i = blockIdx.x * blockDim.x + threadIdx.x;
    int wid = threadIdx.x >> 5, lid = threadIdx.x & 31;
    float v0 = 0.f, v1 = 0.f, v2 = 0.f, v3 = 0.f, v4 = 0.f, v5 = 0.f;

    if (i < Mf + Nf) {   // concat order: [src scores | ref scores]
        float pred; int gt; int fidx;
        if (i < Mf) { pred = p2p_src[i];      fidx = F_SRCFT + i; }
        else        { pred = p2p_ref[i - Mf]; fidx = F_REFF + (i - Mf); }
        gt = g_flags[fidx];
        g_flags[fidx] = 0;                       // self-clean
        float bce = gt ? -logf(pred) : -log1pf(-pred);
        v0 = (float)gt;
        v1 = gt ? bce : 0.f;
        v2 = gt ? 0.f : bce;
    }
    if (i < Mc + Nc) {
        float pred; int gt; int fidx;
        if (i < Mc) { pred = n2p_src[i];      fidx = F_SRCCT + i; }
        else        { pred = n2p_ref[i - Mc]; fidx = F_REFC + (i - Mc); }
        gt = g_flags[fidx];
        g_flags[fidx] = 0;                       // self-clean
        float bce = gt ? -logf(pred) : -log1pf(-pred);
        v3 = (float)gt;
        v4 = gt ? bce : 0.f;
        v5 = gt ? 0.f : bce;
    }
    if (i < Mf) {
        g_counts[cell_of(g_srcft[i])] = 0;       // self-clean touched grid cells
    }

    #pragma unroll
    for (int off = 16; off; off >>= 1) {
        v0 += __shfl_down_sync(0xffffffffu, v0, off);
        v1 += __shfl_down_sync(0xffffffffu, v1, off);
        v2 += __shfl_down_sync(0xffffffffu, v2, off);
        v3 += __shfl_down_sync(0xffffffffu, v3, off);
        v4 += __shfl_down_sync(0xffffffffu, v4, off);
        v5 += __shfl_down_sync(0xffffffffu, v5, off);
    }
    if (lid == 0) {
        s_red[wid][0] = v0; s_red[wid][1] = v1; s_red[wid][2] = v2;
        s_red[wid][3] = v3; s_red[wid][4] = v4; s_red[wid][5] = v5;
    }
    __syncthreads();

    // fold 8 warps -> 1, store block partial (plain stores, distinct addresses)
    if (threadIdx.x < 6) {
        float acc = 0.f;
        #pragma unroll
        for (int w = 0; w < 8; w++) acc += s_red[w][threadIdx.x];
        g_part[blockIdx.x][threadIdx.x] = acc;
    }
    __syncthreads();
    if (threadIdx.x == 0) {
        __threadfence();
        s_last = (atomicAdd(&g_done, 1) == (int)gridDim.x - 1);
    }
    __syncthreads();
    if (!s_last) return;

    // ---- last block: sum all partials and finalize ----
    int nb = (int)gridDim.x;
    float a0=0.f,a1=0.f,a2=0.f,a3=0.f,a4=0.f,a5=0.f;
    for (int b = (int)threadIdx.x; b < nb; b += 256) {
        volatile float* p = g_part[b];
        a0 += p[0]; a1 += p[1]; a2 += p[2];
        a3 += p[3]; a4 += p[4]; a5 += p[5];
    }
    #pragma unroll
    for (int off = 16; off; off >>= 1) {
        a0 += __shfl_down_sync(0xffffffffu, a0, off);
        a1 += __shfl_down_sync(0xffffffffu, a1, off);
        a2 += __shfl_down_sync(0xffffffffu, a2, off);
        a3 += __shfl_down_sync(0xffffffffu, a3, off);
        a4 += __shfl_down_sync(0xffffffffu, a4, off);
        a5 += __shfl_down_sync(0xffffffffu, a5, off);
    }
    if (lid == 0) {
        s_red[wid][0] = a0; s_red[wid][1] = a1; s_red[wid][2] = a2;
        s_red[wid][3] = a3; s_red[wid][4] = a4; s_red[wid][5] = a5;
    }
    __syncthreads();
    if (threadIdx.x == 0) {
        float S1=0.f,Sp=0.f,Sn=0.f,T1=0.f,Tp=0.f,Tn=0.f;
        #pragma unroll
        for (int w = 0; w < 8; w++) {
            S1 += s_red[w][0]; Sp += s_red[w][1]; Sn += s_red[w][2];
            T1 += s_red[w][3]; Tp += s_red[w][4]; Tn += s_red[w][5];
        }
        int np2p = Nf + Mf, nn2p = Nc + Mc;
        float wneg = S1 / (float)np2p;
        float p2p = ((1.0f - wneg) * Sp + wneg * Sn) / (float)np2p;
        float wneg2 = T1 / (float)nn2p;
        float n2p = ((1.0f - wneg2) * Tp + wneg2 * Tn) / (float)nn2p;
        out[0] = n2p;
        out[1] = p2p;
        g_done = 0;                              // self-clean for next replay
    }
}

static inline int imax_(int a, int b) { return a > b ? a : b; }

extern "C" void kernel_launch(void* const* d_in, const int* in_sizes, int n_in,
                              void* d_out, int out_size) {
    const float* rc = (const float*)d_in[0]; int Nc = in_sizes[0] / 3;
    const float* sc = (const float*)d_in[1]; int Mc = in_sizes[1] / 3;
    const float* rf = (const float*)d_in[2]; int Nf = in_sizes[2] / 3;
    const float* sf = (const float*)d_in[3]; int Mf = in_sizes[3] / 3;
    const float* T  = (const float*)d_in[4];
    const float* p2p_ref = (const float*)d_in[5];
    const float* p2p_src = (const float*)d_in[6];
    const float* n2p_ref = (const float*)d_in[7];
    const float* n2p_src = (const float*)d_in[8];
    float* out = (float*)d_out;

    if (Nf > CAP_F) Nf = CAP_F;
    if (Mf > CAP_F) Mf = CAP_F;
    if (Nc > CAP_C) Nc = CAP_C;
    if (Mc > CAP_C) Mc = CAP_C;

    // setup: transform & precompute h + scatter into (pre-zeroed) grid
    int tot = Nf + Mf + Nc + Mc;
    setup_kernel<<<(tot + 255) / 256, 256>>>(rf, Nf, sf, Mf, rc, Nc, sc, Mc, T);

    // fat kernel: coarse (n2p, thr=0.5) + fine (p2p, thr=0.1)
    {
        int qb = (imax_(Nc, Mc) + THREADS - 1) / THREADS;
        int zb = (imax_(Nf, Mf) + TILE - 1) / TILE;
        int nCoarse = qb * zb * 2;
        int nFine = (Nf * 9 + THREADS - 1) / THREADS;
        fat_kernel<<<nCoarse + nFine, THREADS>>>(
            Nc, Mc, Nf, Mf, qb, zb, nCoarse,
            0.5f * 0.5f * 0.5f,          // coarse: 0.5*thr^2, thr=0.5
            0.5f * 0.1f * 0.1f,          // fine:   0.5*thr^2, thr=0.1
            0.1f * 0.1f * 1.0002f);      // fine box-prune threshold with margin
    }

    int nmax = imax_(Nf + Mf, Nc + Mc);
    int nblk = (nmax + 255) / 256;
    if (nblk > MAXPART) nblk = MAXPART;   // 32768/256 = 128 <= MAXPART
    reduce_kernel<<<nblk, 256>>>(p2p_ref, p2p_src, n2p_ref, n2p_src,
                                 Nf, Mf, Nc, Mc, out);
}